// round 7
// baseline (speedup 1.0000x reference)
#include <cuda_runtime.h>
#include <cuda_bf16.h>
#include <cstdint>

#define BATCH 4
#define CIN   64
#define HH    128
#define WW    128
#define COUT  128
#define HW    (HH*WW)        // 16384
#define NPX   (BATCH*HW)     // 65536

// ---------------- scratch (device globals; no allocation allowed) ----------------
__device__ float  g_xt[BATCH*HW*CIN];     // x transposed to NHWC: [b][h][w][c]
__device__ int    g_ppi[9*NPX];           // packed clamped corner coords per (k, pixel)
__device__ float4 g_ppw[9*NPX];           // bilinear weights (mask+validity folded)
// weights split hi/lo, padded pitch-72 layout: [k][o][72] bf16
__device__ __align__(16) __nv_bfloat16 g_wbh[9*128*72];
__device__ __align__(16) __nv_bfloat16 g_wbl[9*128*72];

// ---------------- helpers ----------------
__device__ __forceinline__ uint32_t smem_u32(const void* p) {
    uint32_t a;
    asm("{ .reg .u64 t; cvta.to.shared.u64 t, %1; cvt.u32.u64 %0, t; }" : "=r"(a) : "l"(p));
    return a;
}
__device__ __forceinline__ void ldsm_x4(uint32_t (&r)[4], uint32_t addr) {
    asm volatile("ldmatrix.sync.aligned.m8n8.x4.shared.b16 {%0, %1, %2, %3}, [%4];"
                 : "=r"(r[0]), "=r"(r[1]), "=r"(r[2]), "=r"(r[3]) : "r"(addr));
}
__device__ __forceinline__ void mma16816(float (&d)[4], const uint32_t (&a)[4],
                                         uint32_t b0, uint32_t b1) {
    asm volatile(
        "mma.sync.aligned.m16n8k16.row.col.f32.bf16.bf16.f32 "
        "{%0, %1, %2, %3}, {%4, %5, %6, %7}, {%8, %9}, {%0, %1, %2, %3};"
        : "+f"(d[0]), "+f"(d[1]), "+f"(d[2]), "+f"(d[3])
        : "r"(a[0]), "r"(a[1]), "r"(a[2]), "r"(a[3]), "r"(b0), "r"(b1));
}
__device__ __forceinline__ void cp_async16(uint32_t saddr, const void* g) {
    asm volatile("cp.async.cg.shared.global [%0], [%1], 16;" :: "r"(saddr), "l"(g));
}

// ---------------- kernel: transpose x (NCHW -> NHWC) ----------------
__global__ __launch_bounds__(256) void k_transpose_x(const float* __restrict__ x) {
    __shared__ float tile[64*129];
    int bid = blockIdx.x;              // b*128 + h
    int b = bid >> 7, h = bid & 127;
    int t = threadIdx.x;
    const float* xp = x + ((size_t)b*64*HW) + (size_t)h*WW;
    for (int i = t; i < 64*128; i += 256) {
        int c = i >> 7, w = i & 127;
        tile[c*129 + w] = xp[(size_t)c*HW + w];
    }
    __syncthreads();
    float4* out4 = (float4*)g_xt;
    for (int i = t; i < 2048; i += 256) {
        int w = i >> 4, cq = i & 15;
        float4 v;
        v.x = tile[(cq*4+0)*129 + w];
        v.y = tile[(cq*4+1)*129 + w];
        v.z = tile[(cq*4+2)*129 + w];
        v.w = tile[(cq*4+3)*129 + w];
        out4[(size_t)(bid*128 + w)*16 + cq] = v;
    }
}

// ---------------- kernel: weight split hi/lo, (O,C,9) -> [k][o][72] ----------------
__global__ __launch_bounds__(256) void k_wsplit(const float* __restrict__ weight) {
    int idx = blockIdx.x*256 + threadIdx.x;
    if (idx < 9*128*72) {
        int k = idx / 9216;
        int r = idx - k*9216;
        int o = r / 72, c = r - o*72;
        float v = (c < 64) ? weight[(o*64 + c)*9 + k] : 0.f;
        __nv_bfloat16 hi = __float2bfloat16_rn(v);
        __nv_bfloat16 lo = __float2bfloat16_rn(v - __bfloat162float(hi));
        g_wbh[idx] = hi;
        g_wbl[idx] = lo;
    }
}

// ---------------- kernel: offset/mask conv + sampling-parameter precompute ----------------
// grid (4, 16, 4): 32x8 pixel tile per block, 256 threads, 1 row per thread.
__global__ __launch_bounds__(256) void k_offset(
    const float* __restrict__ x,
    const float* __restrict__ w_off, const float* __restrict__ b_off,
    const float* __restrict__ w_mask, const float* __restrict__ b_mask)
{
    __shared__ float xs[8*10*34];    // [c][row][col], chunk of 8 channels, 10x34 halo tile
    __shared__ float wsh[27*8*9];    // [co][c][p]
    int t   = threadIdx.x;
    int tx  = t & 31, ty = t >> 5;   // ty in 0..7, one row per thread
    int w0  = blockIdx.x * 32;
    int h0  = blockIdx.y * 8;
    int b   = blockIdx.z;

    float acc[27];
    #pragma unroll
    for (int i = 0; i < 27; ++i) acc[i] = 0.f;

    for (int cc = 0; cc < 8; ++cc) {
        for (int i = t; i < 8*10*34; i += 256) {
            int c = i / 340;
            int rem = i - c*340;
            int r = rem / 34, col = rem - r*34;
            int gy = h0 - 1 + r, gx = w0 - 1 + col;
            float v = 0.f;
            if ((unsigned)gy < 128u && (unsigned)gx < 128u)
                v = x[(size_t)((b*64 + cc*8 + c)*128 + gy)*128 + gx];
            xs[i] = v;
        }
        for (int i = t; i < 27*8*9; i += 256) {
            int co = i / 72;
            int rem = i - co*72;
            int c = rem / 9, p = rem - c*9;
            float v;
            if (co < 18) v = w_off[(co*64 + cc*8 + c)*9 + p];
            else         v = w_mask[((co-18)*64 + cc*8 + c)*9 + p];
            wsh[i] = v;
        }
        __syncthreads();
        for (int c = 0; c < 8; ++c) {
            #pragma unroll
            for (int p = 0; p < 9; ++p) {
                const int ky = p/3, kx = p%3;
                float xv = xs[c*340 + (ty+ky)*34 + tx + kx];
                #pragma unroll
                for (int co = 0; co < 27; ++co)
                    acc[co] += xv * wsh[co*72 + c*9 + p];
            }
        }
        __syncthreads();
    }

    // epilogue: turn (offset, mask) into packed corner coords + bilinear weights
    {
        int hrow  = h0 + ty;
        int wglob = w0 + tx;
        int pxg = ((b << 7) + hrow)*128 + wglob;
        #pragma unroll
        for (int kk = 0; kk < 9; ++kk) {
            float dy = acc[2*kk]   + b_off[2*kk];
            float dx = acc[2*kk+1] + b_off[2*kk+1];
            float mz = acc[18+kk]  + b_mask[kk];
            float m  = 1.0f / (1.0f + __expf(-mz));
            float py  = (float)(hrow  - 1 + kk/3) + dy;
            float pxx = (float)(wglob - 1 + kk%3) + dx;
            float y0f = floorf(py), x0f = floorf(pxx);
            float ly = py - y0f, lx = pxx - x0f;
            int y0 = (int)y0f, x0i = (int)x0f;
            int y1 = y0 + 1,  x1i = x0i + 1;
            float w00 = (1.f-ly)*(1.f-lx)*m;
            float w01 = (1.f-ly)*lx*m;
            float w10 = ly*(1.f-lx)*m;
            float w11 = ly*lx*m;
            if (y0  < 0 || y0  > 127) { w00 = 0.f; w01 = 0.f; }
            if (y1  < 0 || y1  > 127) { w10 = 0.f; w11 = 0.f; }
            if (x0i < 0 || x0i > 127) { w00 = 0.f; w10 = 0.f; }
            if (x1i < 0 || x1i > 127) { w01 = 0.f; w11 = 0.f; }
            int y0c = min(max(y0, 0), 127),  y1c = min(max(y1, 0), 127);
            int x0c = min(max(x0i, 0), 127), x1c = min(max(x1i, 0), 127);
            g_ppi[kk*NPX + pxg] = y0c | (y1c << 8) | (x0c << 16) | (x1c << 24);
            g_ppw[kk*NPX + pxg] = make_float4(w00, w01, w10, w11);
        }
    }
}

// ---------------- kernel: deformable sampling + bf16 split mma.sync GEMM ----------------
// grid 512 (b*128+h), 256 threads (8 warps, 4x2: warp_m in 0..3 -> 32 px, warp_n in 0..1 -> 64 out).
// smem (pitch 144B rows, conflict-free for ldmatrix):
//   A_HI@0 (18432 B), A_LO@18432, B_HI@36864, B_LO@55296; total 73728 B.
#define SA_HI 0
#define SA_LO 18432
#define SB_HI 36864
#define SB_LO 55296
#define SMEM_TOT 73728

__global__ __launch_bounds__(256) void k_deform_mma(float* __restrict__ out) {
    extern __shared__ char sm[];
    uint32_t sb = smem_u32(sm);
    int t    = threadIdx.x;
    int wid  = t >> 5, lane = t & 31;
    int bid  = blockIdx.x;
    int b    = bid >> 7, h = bid & 127;
    const float* xb = g_xt + ((size_t)b << 20);

    int warp_m = wid & 3;        // 0..3: px group of 32
    int warp_n = wid >> 2;       // 0..1: out group of 64
    int m0base = warp_m * 32;
    int n0base = warp_n * 64;

    float acc[2][8][4];          // [mtile][ntile8][frag]
    #pragma unroll
    for (int i = 0; i < 2; ++i)
        #pragma unroll
        for (int j = 0; j < 8; ++j)
            #pragma unroll
            for (int q = 0; q < 4; ++q) acc[i][j][q] = 0.f;

    // ldmatrix lane addressing: m0 = rows 0-7 @k+0, m1 = rows 8-15 @k+0,
    // m2 = rows 0-7 @k+8, m3 = rows 8-15 @k+8
    int lrow = (lane & 7) + ((lane >> 3) & 1) * 8;   // row within 16
    int lcol = (lane & 16) ? 8 : 0;                  // k offset within 16

    for (int k = 0; k < 9; ++k) {
        __syncthreads();   // previous tap's ldmatrix reads done before overwrite
        // ---- stage B tiles via cp.async (overlaps with the gather phase below) ----
        {
            const char* srcH = (const char*)(g_wbh + k*9216);
            const char* srcL = (const char*)(g_wbl + k*9216);
            #pragma unroll
            for (int j = 0; j < 4; ++j) {
                int i = t + j*256;
                cp_async16(sb + SB_HI + i*16, srcH + i*16);
            }
            #pragma unroll
            for (int j = 0; j < 4; ++j) {
                int i = t + j*256;
                cp_async16(sb + SB_LO + i*16, srcL + i*16);
            }
            if (t < 128) {   // remaining 128+128 chunks
                int i = 1024 + t;
                cp_async16(sb + SB_HI + i*16, srcH + i*16);
                cp_async16(sb + SB_LO + i*16, srcL + i*16);
            }
            asm volatile("cp.async.commit_group;");
        }
        // ---- sampling: 128 px * 16 chunks of 4 channels ----
        {
            int ppb = k*NPX + bid*128;
            #pragma unroll
            for (int j = 0; j < 8; ++j) {
                int task = t + j*256;
                int cq = task & 15, px = task >> 4;
                int    pc = g_ppi[ppb + px];
                float4 wg = g_ppw[ppb + px];
                int y0 =  pc        & 255;
                int y1 = (pc >>  8) & 255;
                int x0 = (pc >> 16) & 255;
                int x1 = (pc >> 24) & 255;
                const float4* r00 = (const float4*)(xb + (size_t)(((y0<<7)+x0)<<6)) + cq;
                const float4* r01 = (const float4*)(xb + (size_t)(((y0<<7)+x1)<<6)) + cq;
                const float4* r10 = (const float4*)(xb + (size_t)(((y1<<7)+x0)<<6)) + cq;
                const float4* r11 = (const float4*)(xb + (size_t)(((y1<<7)+x1)<<6)) + cq;
                float4 a = *r00, bb = *r01, cc = *r10, dd = *r11;
                float4 v;
                v.x = wg.x*a.x + wg.y*bb.x + wg.z*cc.x + wg.w*dd.x;
                v.y = wg.x*a.y + wg.y*bb.y + wg.z*cc.y + wg.w*dd.y;
                v.z = wg.x*a.z + wg.y*bb.z + wg.z*cc.z + wg.w*dd.z;
                v.w = wg.x*a.w + wg.y*bb.w + wg.z*cc.w + wg.w*dd.w;
                __nv_bfloat16 hx = __float2bfloat16_rn(v.x), hy = __float2bfloat16_rn(v.y);
                __nv_bfloat16 hz = __float2bfloat16_rn(v.z), hw = __float2bfloat16_rn(v.w);
                __nv_bfloat16 lx2 = __float2bfloat16_rn(v.x - __bfloat162float(hx));
                __nv_bfloat16 ly2 = __float2bfloat16_rn(v.y - __bfloat162float(hy));
                __nv_bfloat16 lz2 = __float2bfloat16_rn(v.z - __bfloat162float(hz));
                __nv_bfloat16 lw2 = __float2bfloat16_rn(v.w - __bfloat162float(hw));
                uint32_t h01 = ((uint32_t)__bfloat16_as_ushort(hy) << 16) | __bfloat16_as_ushort(hx);
                uint32_t h23 = ((uint32_t)__bfloat16_as_ushort(hw) << 16) | __bfloat16_as_ushort(hz);
                uint32_t l01 = ((uint32_t)__bfloat16_as_ushort(ly2) << 16) | __bfloat16_as_ushort(lx2);
                uint32_t l23 = ((uint32_t)__bfloat16_as_ushort(lw2) << 16) | __bfloat16_as_ushort(lz2);
                int off = px*144 + cq*8;
                *(uint2*)(sm + SA_HI + off) = make_uint2(h01, h23);
                *(uint2*)(sm + SA_LO + off) = make_uint2(l01, l23);
            }
        }
        asm volatile("cp.async.wait_group 0;" ::: "memory");
        __syncthreads();

        // ---- MMA: 4 ksteps of 16, split passes; B frags loaded per n-group ----
        #pragma unroll
        for (int ks = 0; ks < 4; ++ks) {
            int kc = ks*16 + lcol;
            uint32_t ah[2][4], al[2][4];
            #pragma unroll
            for (int mt = 0; mt < 2; ++mt) {
                uint32_t aoff = (uint32_t)((m0base + mt*16 + lrow)*144 + kc*2);
                ldsm_x4(ah[mt], sb + SA_HI + aoff);
                ldsm_x4(al[mt], sb + SA_LO + aoff);
            }
            #pragma unroll
            for (int ng = 0; ng < 4; ++ng) {
                uint32_t bh[4], bl[4];
                uint32_t boff = (uint32_t)((n0base + ng*16 + lrow)*144 + kc*2);
                ldsm_x4(bh, sb + SB_HI + boff);
                ldsm_x4(bl, sb + SB_LO + boff);
                // B fragment pairing: n-octet 0 = (r0, r2), n-octet 1 = (r1, r3)
                #pragma unroll
                for (int mt = 0; mt < 2; ++mt) {
                    mma16816(acc[mt][2*ng],   ah[mt], bh[0], bh[2]);
                    mma16816(acc[mt][2*ng+1], ah[mt], bh[1], bh[3]);
                    mma16816(acc[mt][2*ng],   al[mt], bh[0], bh[2]);
                    mma16816(acc[mt][2*ng+1], al[mt], bh[1], bh[3]);
                    mma16816(acc[mt][2*ng],   ah[mt], bl[0], bl[2]);
                    mma16816(acc[mt][2*ng+1], ah[mt], bl[1], bl[3]);
                }
            }
        }
    }

    // ---- epilogue: frags -> smem [o][px] (pitch 132, conflict-free), coalesced stores ----
    __syncthreads();
    float* smo = (float*)sm;
    int qrow = lane >> 2, qcol = (lane & 3) * 2;
    #pragma unroll
    for (int mt = 0; mt < 2; ++mt) {
        #pragma unroll
        for (int nt = 0; nt < 8; ++nt) {
            int px0 = m0base + mt*16 + qrow;
            int o0  = n0base + nt*8 + qcol;
            smo[ o0     *132 + px0    ] = acc[mt][nt][0];
            smo[(o0 + 1)*132 + px0    ] = acc[mt][nt][1];
            smo[ o0     *132 + px0 + 8] = acc[mt][nt][2];
            smo[(o0 + 1)*132 + px0 + 8] = acc[mt][nt][3];
        }
    }
    __syncthreads();
    float* op = out + ((size_t)b*128)*16384 + (size_t)h*128;
    #pragma unroll
    for (int j = 0; j < 16; ++j) {
        int idx = t + j*256;
        int o = idx >> 5, pq = idx & 31;
        float4 v = *(const float4*)(smo + o*132 + pq*4);
        *(float4*)(op + (size_t)o*16384 + pq*4) = v;
    }
}

// ---------------- launch ----------------
extern "C" void kernel_launch(void* const* d_in, const int* in_sizes, int n_in,
                              void* d_out, int out_size) {
    const float* x      = (const float*)d_in[0];
    const float* w_off  = (const float*)d_in[1];
    const float* b_off  = (const float*)d_in[2];
    const float* w_mask = (const float*)d_in[3];
    const float* b_mask = (const float*)d_in[4];
    const float* weight = (const float*)d_in[5];
    float* out = (float*)d_out;

    (void)cudaFuncSetAttribute(k_deform_mma, cudaFuncAttributeMaxDynamicSharedMemorySize, SMEM_TOT);

    k_transpose_x<<<512, 256>>>(x);
    k_wsplit<<<(9*128*72 + 255)/256, 256>>>(weight);
    k_offset<<<dim3(4, 16, 4), 256>>>(x, w_off, b_off, w_mask, b_mask);
    k_deform_mma<<<512, 256, SMEM_TOT>>>(out);
}

// round 9
// speedup vs baseline: 1.2078x; 1.2078x over previous
#include <cuda_runtime.h>
#include <cuda_bf16.h>
#include <cstdint>

#define BATCH 4
#define CIN   64
#define HH    128
#define WW    128
#define COUT  128
#define HW    (HH*WW)        // 16384
#define NPX   (BATCH*HW)     // 65536

// ---------------- scratch (device globals; no allocation allowed) ----------------
__device__ float  g_xt[BATCH*HW*CIN];     // x transposed to NHWC: [b][h][w][c]
__device__ int    g_ppi[9*NPX];           // packed clamped corner coords per (k, pixel)
__device__ float4 g_ppw[9*NPX];           // bilinear weights (mask+validity folded)
// weights split hi/lo, padded pitch-72 layout: [k][o][72] bf16
__device__ __align__(16) __nv_bfloat16 g_wbh[9*128*72];
__device__ __align__(16) __nv_bfloat16 g_wbl[9*128*72];

// ---------------- helpers ----------------
__device__ __forceinline__ uint32_t smem_u32(const void* p) {
    uint32_t a;
    asm("{ .reg .u64 t; cvta.to.shared.u64 t, %1; cvt.u32.u64 %0, t; }" : "=r"(a) : "l"(p));
    return a;
}
__device__ __forceinline__ void ldsm_x4(uint32_t (&r)[4], uint32_t addr) {
    asm volatile("ldmatrix.sync.aligned.m8n8.x4.shared.b16 {%0, %1, %2, %3}, [%4];"
                 : "=r"(r[0]), "=r"(r[1]), "=r"(r[2]), "=r"(r[3]) : "r"(addr));
}
__device__ __forceinline__ void mma16816(float (&d)[4], const uint32_t (&a)[4],
                                         uint32_t b0, uint32_t b1) {
    asm volatile(
        "mma.sync.aligned.m16n8k16.row.col.f32.bf16.bf16.f32 "
        "{%0, %1, %2, %3}, {%4, %5, %6, %7}, {%8, %9}, {%0, %1, %2, %3};"
        : "+f"(d[0]), "+f"(d[1]), "+f"(d[2]), "+f"(d[3])
        : "r"(a[0]), "r"(a[1]), "r"(a[2]), "r"(a[3]), "r"(b0), "r"(b1));
}
__device__ __forceinline__ void cp_async16(uint32_t saddr, const void* g) {
    asm volatile("cp.async.cg.shared.global [%0], [%1], 16;" :: "r"(saddr), "l"(g));
}

// ---------------- kernel: transpose x (NCHW -> NHWC) ----------------
__global__ __launch_bounds__(256) void k_transpose_x(const float* __restrict__ x) {
    __shared__ float tile[64*129];
    int bid = blockIdx.x;              // b*128 + h
    int b = bid >> 7, h = bid & 127;
    int t = threadIdx.x;
    const float* xp = x + ((size_t)b*64*HW) + (size_t)h*WW;
    for (int i = t; i < 64*128; i += 256) {
        int c = i >> 7, w = i & 127;
        tile[c*129 + w] = xp[(size_t)c*HW + w];
    }
    __syncthreads();
    float4* out4 = (float4*)g_xt;
    for (int i = t; i < 2048; i += 256) {
        int w = i >> 4, cq = i & 15;
        float4 v;
        v.x = tile[(cq*4+0)*129 + w];
        v.y = tile[(cq*4+1)*129 + w];
        v.z = tile[(cq*4+2)*129 + w];
        v.w = tile[(cq*4+3)*129 + w];
        out4[(size_t)(bid*128 + w)*16 + cq] = v;
    }
}

// ---------------- kernel: weight split hi/lo, (O,C,9) -> [k][o][72] ----------------
__global__ __launch_bounds__(256) void k_wsplit(const float* __restrict__ weight) {
    int idx = blockIdx.x*256 + threadIdx.x;
    if (idx < 9*128*72) {
        int k = idx / 9216;
        int r = idx - k*9216;
        int o = r / 72, c = r - o*72;
        float v = (c < 64) ? weight[(o*64 + c)*9 + k] : 0.f;
        __nv_bfloat16 hi = __float2bfloat16_rn(v);
        __nv_bfloat16 lo = __float2bfloat16_rn(v - __bfloat162float(hi));
        g_wbh[idx] = hi;
        g_wbl[idx] = lo;
    }
}

// ---------------- kernel: offset/mask conv + sampling-parameter precompute ----------------
// grid (4, 16, 4): 32x8 pixel tile per block, 128 threads, 2 rows per thread (R5 config).
__global__ __launch_bounds__(128) void k_offset(
    const float* __restrict__ x,
    const float* __restrict__ w_off, const float* __restrict__ b_off,
    const float* __restrict__ w_mask, const float* __restrict__ b_mask)
{
    __shared__ float xs[8*10*34];    // [c][row][col], chunk of 8 channels, 10x34 halo tile
    __shared__ float wsh[27*8*9];    // [co][c][p]
    int t   = threadIdx.x;
    int tx  = t & 31, tyg = t >> 5;  // tyg in 0..3; thread owns rows tyg and tyg+4
    int w0  = blockIdx.x * 32;
    int h0  = blockIdx.y * 8;
    int b   = blockIdx.z;

    float acc0[27], acc1[27];
    #pragma unroll
    for (int i = 0; i < 27; ++i) { acc0[i] = 0.f; acc1[i] = 0.f; }

    for (int cc = 0; cc < 8; ++cc) {
        for (int i = t; i < 8*10*34; i += 128) {
            int c = i / 340;
            int rem = i - c*340;
            int r = rem / 34, col = rem - r*34;
            int gy = h0 - 1 + r, gx = w0 - 1 + col;
            float v = 0.f;
            if ((unsigned)gy < 128u && (unsigned)gx < 128u)
                v = x[(size_t)((b*64 + cc*8 + c)*128 + gy)*128 + gx];
            xs[i] = v;
        }
        for (int i = t; i < 27*8*9; i += 128) {
            int co = i / 72;
            int rem = i - co*72;
            int c = rem / 9, p = rem - c*9;
            float v;
            if (co < 18) v = w_off[(co*64 + cc*8 + c)*9 + p];
            else         v = w_mask[((co-18)*64 + cc*8 + c)*9 + p];
            wsh[i] = v;
        }
        __syncthreads();
        for (int c = 0; c < 8; ++c) {
            #pragma unroll
            for (int p = 0; p < 9; ++p) {
                const int ky = p/3, kx = p%3;
                float xv0 = xs[c*340 + (tyg+ky)*34   + tx + kx];
                float xv1 = xs[c*340 + (tyg+4+ky)*34 + tx + kx];
                #pragma unroll
                for (int co = 0; co < 27; ++co) {
                    float wv = wsh[co*72 + c*9 + p];
                    acc0[co] += xv0 * wv;
                    acc1[co] += xv1 * wv;
                }
            }
        }
        __syncthreads();
    }

    auto epi = [&](float (&A)[27], int hrow) {
        int wglob = w0 + tx;
        int pxg = ((b << 7) + hrow)*128 + wglob;
        #pragma unroll
        for (int kk = 0; kk < 9; ++kk) {
            float dy = A[2*kk]   + b_off[2*kk];
            float dx = A[2*kk+1] + b_off[2*kk+1];
            float mz = A[18+kk]  + b_mask[kk];
            float m  = 1.0f / (1.0f + __expf(-mz));
            float py  = (float)(hrow  - 1 + kk/3) + dy;
            float pxx = (float)(wglob - 1 + kk%3) + dx;
            float y0f = floorf(py), x0f = floorf(pxx);
            float ly = py - y0f, lx = pxx - x0f;
            int y0 = (int)y0f, x0i = (int)x0f;
            int y1 = y0 + 1,  x1i = x0i + 1;
            float w00 = (1.f-ly)*(1.f-lx)*m;
            float w01 = (1.f-ly)*lx*m;
            float w10 = ly*(1.f-lx)*m;
            float w11 = ly*lx*m;
            if (y0  < 0 || y0  > 127) { w00 = 0.f; w01 = 0.f; }
            if (y1  < 0 || y1  > 127) { w10 = 0.f; w11 = 0.f; }
            if (x0i < 0 || x0i > 127) { w00 = 0.f; w10 = 0.f; }
            if (x1i < 0 || x1i > 127) { w01 = 0.f; w11 = 0.f; }
            int y0c = min(max(y0, 0), 127),  y1c = min(max(y1, 0), 127);
            int x0c = min(max(x0i, 0), 127), x1c = min(max(x1i, 0), 127);
            g_ppi[kk*NPX + pxg] = y0c | (y1c << 8) | (x0c << 16) | (x1c << 24);
            g_ppw[kk*NPX + pxg] = make_float4(w00, w01, w10, w11);
        }
    };
    epi(acc0, h0 + tyg);
    epi(acc1, h0 + tyg + 4);
}

// ---------------- kernel: deformable sampling + bf16 split mma.sync GEMM ----------------
// grid 1024 (b, h, half-row), 256 threads (8 warps, 2x4: warp_m -> 32 px, warp_n -> 32 out).
// Block tile: M=64 px, N=128 out, K=576. acc = 32 regs/thread -> 3 CTAs/SM.
// smem: A_HI@0 (9216), A_LO@9216, B_HI@18432 (18432), B_LO@36864; total 55296 B.
#define SA_HI 0
#define SA_LO 9216
#define SB_HI 18432
#define SB_LO 36864
#define SMEM_TOT 55296

__global__ __launch_bounds__(256, 3) void k_deform_mma(float* __restrict__ out) {
    extern __shared__ char sm[];
    uint32_t sb = smem_u32(sm);
    int t    = threadIdx.x;
    int wid  = t >> 5, lane = t & 31;
    int bid  = blockIdx.x;                 // b*256 + h*2 + half
    int b    = bid >> 8;
    int rem  = bid & 255;
    int h    = rem >> 1, half = rem & 1;
    const float* xb = g_xt + ((size_t)b << 20);

    int warp_m = wid & 1;        // 0..1: px group of 32
    int warp_n = wid >> 1;       // 0..3: out group of 32
    int m0base = warp_m * 32;
    int n0base = warp_n * 32;

    float acc[2][4][4];          // [mtile16][n8tile][frag]
    #pragma unroll
    for (int i = 0; i < 2; ++i)
        #pragma unroll
        for (int j = 0; j < 4; ++j)
            #pragma unroll
            for (int q = 0; q < 4; ++q) acc[i][j][q] = 0.f;

    // ldmatrix lane addressing: m0 = rows 0-7 @k+0, m1 = rows 8-15 @k+0,
    // m2 = rows 0-7 @k+8, m3 = rows 8-15 @k+8
    int lrow = (lane & 7) + ((lane >> 3) & 1) * 8;   // row within 16
    int lcol = (lane & 16) ? 8 : 0;                  // k offset within 16

    for (int k = 0; k < 9; ++k) {
        __syncthreads();   // previous tap's ldmatrix reads done before overwrite
        // ---- stage B tiles via cp.async (overlaps with the gather phase below) ----
        {
            const char* srcH = (const char*)(g_wbh + k*9216);
            const char* srcL = (const char*)(g_wbl + k*9216);
            #pragma unroll
            for (int j = 0; j < 4; ++j) {
                int i = t + j*256;
                cp_async16(sb + SB_HI + i*16, srcH + i*16);
            }
            #pragma unroll
            for (int j = 0; j < 4; ++j) {
                int i = t + j*256;
                cp_async16(sb + SB_LO + i*16, srcL + i*16);
            }
            if (t < 128) {   // remaining 128+128 chunks
                int i = 1024 + t;
                cp_async16(sb + SB_HI + i*16, srcH + i*16);
                cp_async16(sb + SB_LO + i*16, srcL + i*16);
            }
            asm volatile("cp.async.commit_group;");
        }
        // ---- sampling: 64 px * 16 chunks of 4 channels = 1024 tasks, 4/thread ----
        {
            int ppb = k*NPX + (((b << 7) + h) << 7) + half*64;
            #pragma unroll
            for (int j = 0; j < 4; ++j) {
                int task = t + j*256;
                int cq = task & 15, px = task >> 4;
                int    pc = g_ppi[ppb + px];
                float4 wg = g_ppw[ppb + px];
                int y0 =  pc        & 255;
                int y1 = (pc >>  8) & 255;
                int x0 = (pc >> 16) & 255;
                int x1 = (pc >> 24) & 255;
                const float4* r00 = (const float4*)(xb + (size_t)(((y0<<7)+x0)<<6)) + cq;
                const float4* r01 = (const float4*)(xb + (size_t)(((y0<<7)+x1)<<6)) + cq;
                const float4* r10 = (const float4*)(xb + (size_t)(((y1<<7)+x0)<<6)) + cq;
                const float4* r11 = (const float4*)(xb + (size_t)(((y1<<7)+x1)<<6)) + cq;
                float4 a = *r00, bb = *r01, cc = *r10, dd = *r11;
                float4 v;
                v.x = wg.x*a.x + wg.y*bb.x + wg.z*cc.x + wg.w*dd.x;
                v.y = wg.x*a.y + wg.y*bb.y + wg.z*cc.y + wg.w*dd.y;
                v.z = wg.x*a.z + wg.y*bb.z + wg.z*cc.z + wg.w*dd.z;
                v.w = wg.x*a.w + wg.y*bb.w + wg.z*cc.w + wg.w*dd.w;
                __nv_bfloat16 hx = __float2bfloat16_rn(v.x), hy = __float2bfloat16_rn(v.y);
                __nv_bfloat16 hz = __float2bfloat16_rn(v.z), hw = __float2bfloat16_rn(v.w);
                __nv_bfloat16 lx2 = __float2bfloat16_rn(v.x - __bfloat162float(hx));
                __nv_bfloat16 ly2 = __float2bfloat16_rn(v.y - __bfloat162float(hy));
                __nv_bfloat16 lz2 = __float2bfloat16_rn(v.z - __bfloat162float(hz));
                __nv_bfloat16 lw2 = __float2bfloat16_rn(v.w - __bfloat162float(hw));
                uint32_t h01 = ((uint32_t)__bfloat16_as_ushort(hy) << 16) | __bfloat16_as_ushort(hx);
                uint32_t h23 = ((uint32_t)__bfloat16_as_ushort(hw) << 16) | __bfloat16_as_ushort(hz);
                uint32_t l01 = ((uint32_t)__bfloat16_as_ushort(ly2) << 16) | __bfloat16_as_ushort(lx2);
                uint32_t l23 = ((uint32_t)__bfloat16_as_ushort(lw2) << 16) | __bfloat16_as_ushort(lz2);
                int off = px*144 + cq*8;
                *(uint2*)(sm + SA_HI + off) = make_uint2(h01, h23);
                *(uint2*)(sm + SA_LO + off) = make_uint2(l01, l23);
            }
        }
        asm volatile("cp.async.wait_group 0;" ::: "memory");
        __syncthreads();

        // ---- MMA: 4 ksteps of 16, split passes ----
        #pragma unroll
        for (int ks = 0; ks < 4; ++ks) {
            int kc = ks*16 + lcol;
            uint32_t ah[2][4], al[2][4];
            #pragma unroll
            for (int mt = 0; mt < 2; ++mt) {
                uint32_t aoff = (uint32_t)((m0base + mt*16 + lrow)*144 + kc*2);
                ldsm_x4(ah[mt], sb + SA_HI + aoff);
                ldsm_x4(al[mt], sb + SA_LO + aoff);
            }
            #pragma unroll
            for (int ng = 0; ng < 2; ++ng) {
                uint32_t bh[4], bl[4];
                uint32_t boff = (uint32_t)((n0base + ng*16 + lrow)*144 + kc*2);
                ldsm_x4(bh, sb + SB_HI + boff);
                ldsm_x4(bl, sb + SB_LO + boff);
                // B fragment pairing: n-octet 0 = (r0, r2), n-octet 1 = (r1, r3)
                #pragma unroll
                for (int mt = 0; mt < 2; ++mt) {
                    mma16816(acc[mt][2*ng],   ah[mt], bh[0], bh[2]);
                    mma16816(acc[mt][2*ng+1], ah[mt], bh[1], bh[3]);
                    mma16816(acc[mt][2*ng],   al[mt], bh[0], bh[2]);
                    mma16816(acc[mt][2*ng+1], al[mt], bh[1], bh[3]);
                    mma16816(acc[mt][2*ng],   ah[mt], bl[0], bl[2]);
                    mma16816(acc[mt][2*ng+1], ah[mt], bl[1], bl[3]);
                }
            }
        }
    }

    // ---- epilogue: frags -> smem [o][px] (pitch 68, conflict-free), coalesced stores ----
    __syncthreads();
    float* smo = (float*)sm;   // 128 o x 68 px: 128*68*4 = 34816 B
    int qrow = lane >> 2, qcol = (lane & 3) * 2;
    #pragma unroll
    for (int mt = 0; mt < 2; ++mt) {
        #pragma unroll
        for (int nt = 0; nt < 4; ++nt) {
            int px0 = m0base + mt*16 + qrow;
            int o0  = n0base + nt*8 + qcol;
            smo[ o0     *68 + px0    ] = acc[mt][nt][0];
            smo[(o0 + 1)*68 + px0    ] = acc[mt][nt][1];
            smo[ o0     *68 + px0 + 8] = acc[mt][nt][2];
            smo[(o0 + 1)*68 + px0 + 8] = acc[mt][nt][3];
        }
    }
    __syncthreads();
    float* op = out + ((size_t)b*128)*16384 + (size_t)h*128 + half*64;
    #pragma unroll
    for (int j = 0; j < 8; ++j) {
        int idx = t + j*256;
        int o = idx >> 4, pq = idx & 15;
        float4 v = *(const float4*)(smo + o*68 + pq*4);
        *(float4*)(op + (size_t)o*16384 + pq*4) = v;
    }
}

// ---------------- launch ----------------
extern "C" void kernel_launch(void* const* d_in, const int* in_sizes, int n_in,
                              void* d_out, int out_size) {
    const float* x      = (const float*)d_in[0];
    const float* w_off  = (const float*)d_in[1];
    const float* b_off  = (const float*)d_in[2];
    const float* w_mask = (const float*)d_in[3];
    const float* b_mask = (const float*)d_in[4];
    const float* weight = (const float*)d_in[5];
    float* out = (float*)d_out;

    (void)cudaFuncSetAttribute(k_deform_mma, cudaFuncAttributeMaxDynamicSharedMemorySize, SMEM_TOT);

    k_transpose_x<<<512, 256>>>(x);
    k_wsplit<<<(9*128*72 + 255)/256, 256>>>(weight);
    k_offset<<<dim3(4, 16, 4), 128>>>(x, w_off, b_off, w_mask, b_mask);
    k_deform_mma<<<1024, 256, SMEM_TOT>>>(out);
}

// round 11
// speedup vs baseline: 1.6935x; 1.4022x over previous
#include <cuda_runtime.h>
#include <cuda_bf16.h>
#include <cstdint>

#define BATCH 4
#define CIN   64
#define HH    128
#define WW    128
#define COUT  128
#define HW    (HH*WW)        // 16384
#define NPX   (BATCH*HW)     // 65536

// ---------------- scratch (device globals; no allocation allowed) ----------------
__device__ float  g_xt[BATCH*HW*CIN];     // x transposed to NHWC fp32: [b][h][w][c]
__device__ __align__(16) __nv_bfloat16 g_xbh[BATCH*HW*CIN];  // x NHWC bf16 hi
__device__ __align__(16) __nv_bfloat16 g_xbl[BATCH*HW*CIN];  // x NHWC bf16 lo
__device__ int    g_ppi[9*NPX];           // packed clamped corner coords per (k, pixel)
__device__ float4 g_ppw[9*NPX];           // bilinear weights (mask+validity folded)
// main weights split hi/lo, padded pitch-72 layout: [k][o][72] bf16
__device__ __align__(16) __nv_bfloat16 g_wbh[9*128*72];
__device__ __align__(16) __nv_bfloat16 g_wbl[9*128*72];
// offset/mask conv weights split hi/lo: [k][32][72] bf16 (rows 0-17 w_off, 18-26 w_mask, rest 0)
__device__ __align__(16) __nv_bfloat16 g_obh[9*32*72];
__device__ __align__(16) __nv_bfloat16 g_obl[9*32*72];

// ---------------- helpers ----------------
__device__ __forceinline__ uint32_t smem_u32(const void* p) {
    uint32_t a;
    asm("{ .reg .u64 t; cvta.to.shared.u64 t, %1; cvt.u32.u64 %0, t; }" : "=r"(a) : "l"(p));
    return a;
}
__device__ __forceinline__ void ldsm_x4(uint32_t (&r)[4], uint32_t addr) {
    asm volatile("ldmatrix.sync.aligned.m8n8.x4.shared.b16 {%0, %1, %2, %3}, [%4];"
                 : "=r"(r[0]), "=r"(r[1]), "=r"(r[2]), "=r"(r[3]) : "r"(addr));
}
__device__ __forceinline__ void mma16816(float (&d)[4], const uint32_t (&a)[4],
                                         uint32_t b0, uint32_t b1) {
    asm volatile(
        "mma.sync.aligned.m16n8k16.row.col.f32.bf16.bf16.f32 "
        "{%0, %1, %2, %3}, {%4, %5, %6, %7}, {%8, %9}, {%0, %1, %2, %3};"
        : "+f"(d[0]), "+f"(d[1]), "+f"(d[2]), "+f"(d[3])
        : "r"(a[0]), "r"(a[1]), "r"(a[2]), "r"(a[3]), "r"(b0), "r"(b1));
}
__device__ __forceinline__ void cp_async16(uint32_t saddr, const void* g) {
    asm volatile("cp.async.cg.shared.global [%0], [%1], 16;" :: "r"(saddr), "l"(g));
}
__device__ __forceinline__ void cp_async16z(uint32_t saddr, const void* g, uint32_t srcsz) {
    asm volatile("cp.async.cg.shared.global [%0], [%1], 16, %2;" :: "r"(saddr), "l"(g), "r"(srcsz));
}

// ---------------- kernel: transpose x (NCHW -> NHWC fp32 + bf16 hi/lo) ----------------
__global__ __launch_bounds__(256) void k_transpose_x(const float* __restrict__ x) {
    __shared__ float tile[64*129];
    int bid = blockIdx.x;              // b*128 + h
    int b = bid >> 7, h = bid & 127;
    int t = threadIdx.x;
    const float* xp = x + ((size_t)b*64*HW) + (size_t)h*WW;
    for (int i = t; i < 64*128; i += 256) {
        int c = i >> 7, w = i & 127;
        tile[c*129 + w] = xp[(size_t)c*HW + w];
    }
    __syncthreads();
    float4* out4 = (float4*)g_xt;
    uint2* oh = (uint2*)g_xbh;
    uint2* ol = (uint2*)g_xbl;
    for (int i = t; i < 2048; i += 256) {
        int w = i >> 4, cq = i & 15;
        float4 v;
        v.x = tile[(cq*4+0)*129 + w];
        v.y = tile[(cq*4+1)*129 + w];
        v.z = tile[(cq*4+2)*129 + w];
        v.w = tile[(cq*4+3)*129 + w];
        size_t oidx = (size_t)(bid*128 + w)*16 + cq;
        out4[oidx] = v;
        __nv_bfloat16 hx = __float2bfloat16_rn(v.x), hy = __float2bfloat16_rn(v.y);
        __nv_bfloat16 hz = __float2bfloat16_rn(v.z), hw = __float2bfloat16_rn(v.w);
        __nv_bfloat16 lx = __float2bfloat16_rn(v.x - __bfloat162float(hx));
        __nv_bfloat16 ly = __float2bfloat16_rn(v.y - __bfloat162float(hy));
        __nv_bfloat16 lz = __float2bfloat16_rn(v.z - __bfloat162float(hz));
        __nv_bfloat16 lw = __float2bfloat16_rn(v.w - __bfloat162float(hw));
        uint32_t h01 = ((uint32_t)__bfloat16_as_ushort(hy) << 16) | __bfloat16_as_ushort(hx);
        uint32_t h23 = ((uint32_t)__bfloat16_as_ushort(hw) << 16) | __bfloat16_as_ushort(hz);
        uint32_t l01 = ((uint32_t)__bfloat16_as_ushort(ly) << 16) | __bfloat16_as_ushort(lx);
        uint32_t l23 = ((uint32_t)__bfloat16_as_ushort(lw) << 16) | __bfloat16_as_ushort(lz);
        oh[oidx] = make_uint2(h01, h23);
        ol[oidx] = make_uint2(l01, l23);
    }
}

// ---------------- kernel: weight split hi/lo (main + offset/mask) ----------------
__global__ __launch_bounds__(256) void k_wsplit(
    const float* __restrict__ weight,
    const float* __restrict__ w_off, const float* __restrict__ w_mask) {
    int idx = blockIdx.x*256 + threadIdx.x;
    if (idx < 9*128*72) {
        int k = idx / 9216;
        int r = idx - k*9216;
        int o = r / 72, c = r - o*72;
        float v = (c < 64) ? weight[(o*64 + c)*9 + k] : 0.f;
        __nv_bfloat16 hi = __float2bfloat16_rn(v);
        __nv_bfloat16 lo = __float2bfloat16_rn(v - __bfloat162float(hi));
        g_wbh[idx] = hi;
        g_wbl[idx] = lo;
    } else if (idx < 9*128*72 + 9*32*72) {
        int i2 = idx - 9*128*72;
        int k = i2 / 2304;
        int r = i2 - k*2304;
        int o = r / 72, c = r - o*72;
        float v = 0.f;
        if (c < 64) {
            if (o < 18)      v = w_off[(o*64 + c)*9 + k];
            else if (o < 27) v = w_mask[((o-18)*64 + c)*9 + k];
        }
        __nv_bfloat16 hi = __float2bfloat16_rn(v);
        __nv_bfloat16 lo = __float2bfloat16_rn(v - __bfloat162float(hi));
        g_obh[i2] = hi;
        g_obl[i2] = lo;
    }
}

// ---------------- kernel: offset/mask conv via bf16 split MMA + epi ----------------
// grid 512 (b*128+h), 256 threads (8 warps; warp w -> px rows 16w..16w+15).
// Per block: M=128 px, N=32 (27 used), K=576 over 9 taps of 64.
// smem double-buffered: per buf: A_HI@0 (18432), A_LO@18432, B_HI@36864 (4608), B_LO@41472.
// buf stride 46080; total 92160. Epilogue reuses [px][28] fp32 (14336 B).
#define OBUF 46080
#define OB_AHI 0
#define OB_ALO 18432
#define OB_BHI 36864
#define OB_BLO 41472
#define OSMEM_TOT 92160

__global__ __launch_bounds__(256, 2) void k_offset_mma(
    const float* __restrict__ b_off, const float* __restrict__ b_mask)
{
    extern __shared__ char sm[];
    uint32_t sb = smem_u32(sm);
    int t   = threadIdx.x;
    int wid = t >> 5, lane = t & 31;
    int bid = blockIdx.x;              // b*128 + h
    int b = bid >> 7, h = bid & 127;

    float acc[4][4];                   // 4 n-octets (32 cols) x frag
    #pragma unroll
    for (int i = 0; i < 4; ++i)
        #pragma unroll
        for (int q = 0; q < 4; ++q) acc[i][q] = 0.f;

    int lrow = (lane & 7) + ((lane >> 3) & 1) * 8;
    int lcol = (lane & 16) ? 8 : 0;

    // stage tap kk into buffer (kk&1)
    auto stage = [&](int kk) {
        uint32_t base = sb + (kk & 1) * OBUF;
        int ky = kk / 3, kx = kk % 3;
        int hy = h - 1 + ky;
        bool rowok = (unsigned)hy < 128u;
        int hyc = rowok ? hy : 0;
        const char* srcH = (const char*)g_xbh + ((size_t)((b*128 + hyc)*128)) * 128;
        const char* srcL = (const char*)g_xbl + ((size_t)((b*128 + hyc)*128)) * 128;
        // A: 128 px x 8 parts, hi then lo: 2048 chunks / 256 thr = 8 each
        #pragma unroll
        for (int j = 0; j < 8; ++j) {
            int i = t + j*256;
            int half = i >> 10;            // 0 = hi, 1 = lo
            int r = i & 1023;
            int px = r >> 3, part = r & 7;
            int sx = px - 1 + kx;
            bool ok = rowok && ((unsigned)sx < 128u);
            int sxc = ok ? sx : 0;
            uint32_t srcsz = ok ? 16u : 0u;
            const char* src = (half ? srcL : srcH) + (size_t)sxc*128 + part*16;
            uint32_t dst = base + (half ? OB_ALO : OB_AHI) + px*144 + part*16;
            cp_async16z(dst, src, srcsz);
        }
        // B: 288 chunks hi + 288 lo
        #pragma unroll
        for (int j = 0; j < 3; ++j) {
            int i = t + j*256;
            if (i < 576) {
                int half = (i >= 288);
                int r = half ? i - 288 : i;
                const char* src = (const char*)(half ? g_obl : g_obh) + (size_t)kk*4608 + r*16;
                uint32_t dst = base + (half ? OB_BLO : OB_BHI) + r*16;
                cp_async16(dst, src);
            }
        }
        asm volatile("cp.async.commit_group;");
    };

    stage(0);
    for (int k = 0; k < 9; ++k) {
        asm volatile("cp.async.wait_group 0;" ::: "memory");
        __syncthreads();
        if (k < 8) stage(k + 1);
        uint32_t base = sb + (k & 1) * OBUF;
        // MMA on buffer k
        #pragma unroll
        for (int ks = 0; ks < 4; ++ks) {
            int kc = ks*16 + lcol;
            uint32_t ah[4], al[4];
            uint32_t aoff = (uint32_t)((wid*16 + lrow)*144 + kc*2);
            ldsm_x4(ah, base + OB_AHI + aoff);
            ldsm_x4(al, base + OB_ALO + aoff);
            #pragma unroll
            for (int bt = 0; bt < 2; ++bt) {
                uint32_t bh[4], bl[4];
                uint32_t boff = (uint32_t)((bt*16 + lrow)*144 + kc*2);
                ldsm_x4(bh, base + OB_BHI + boff);
                ldsm_x4(bl, base + OB_BLO + boff);
                mma16816(acc[2*bt],   ah, bh[0], bh[2]);
                mma16816(acc[2*bt+1], ah, bh[1], bh[3]);
                mma16816(acc[2*bt],   al, bh[0], bh[2]);
                mma16816(acc[2*bt+1], al, bh[1], bh[3]);
                mma16816(acc[2*bt],   ah, bl[0], bl[2]);
                mma16816(acc[2*bt+1], ah, bl[1], bl[3]);
            }
        }
    }

    // frags -> smem [px][28]
    __syncthreads();
    float* smo = (float*)sm;
    int qrow = lane >> 2, qcol = (lane & 3) * 2;
    #pragma unroll
    for (int oct = 0; oct < 4; ++oct) {
        int co = oct*8 + qcol;
        if (co < 27) {
            int px0 = wid*16 + qrow;
            smo[px0*28 + co]     = acc[oct][0];
            smo[(px0+8)*28 + co] = acc[oct][2];
            if (co + 1 < 27) {
                smo[px0*28 + co + 1]     = acc[oct][1];
                smo[(px0+8)*28 + co + 1] = acc[oct][3];
            }
        }
    }
    __syncthreads();

    // epi: one thread per pixel
    if (t < 128) {
        int px = t;
        int pxg = ((b << 7) + h)*128 + px;
        #pragma unroll
        for (int kk = 0; kk < 9; ++kk) {
            float dy = smo[px*28 + 2*kk]   + b_off[2*kk];
            float dx = smo[px*28 + 2*kk+1] + b_off[2*kk+1];
            float mz = smo[px*28 + 18+kk]  + b_mask[kk];
            float m  = 1.0f / (1.0f + __expf(-mz));
            float py  = (float)(h  - 1 + kk/3) + dy;
            float pxx = (float)(px - 1 + kk%3) + dx;
            float y0f = floorf(py), x0f = floorf(pxx);
            float ly = py - y0f, lx = pxx - x0f;
            int y0 = (int)y0f, x0i = (int)x0f;
            int y1 = y0 + 1,  x1i = x0i + 1;
            float w00 = (1.f-ly)*(1.f-lx)*m;
            float w01 = (1.f-ly)*lx*m;
            float w10 = ly*(1.f-lx)*m;
            float w11 = ly*lx*m;
            if (y0  < 0 || y0  > 127) { w00 = 0.f; w01 = 0.f; }
            if (y1  < 0 || y1  > 127) { w10 = 0.f; w11 = 0.f; }
            if (x0i < 0 || x0i > 127) { w00 = 0.f; w10 = 0.f; }
            if (x1i < 0 || x1i > 127) { w01 = 0.f; w11 = 0.f; }
            int y0c = min(max(y0, 0), 127),  y1c = min(max(y1, 0), 127);
            int x0c = min(max(x0i, 0), 127), x1c = min(max(x1i, 0), 127);
            g_ppi[kk*NPX + pxg] = y0c | (y1c << 8) | (x0c << 16) | (x1c << 24);
            g_ppw[kk*NPX + pxg] = make_float4(w00, w01, w10, w11);
        }
    }
}

// ---------------- kernel: deformable sampling + bf16 split mma.sync GEMM ----------------
// grid 1024 (b, h, half-row), 256 threads (8 warps, 2x4: warp_m -> 32 px, warp_n -> 32 out).
// Block tile: M=64 px, N=128 out, K=576. 3 CTAs/SM.
#define SA_HI 0
#define SA_LO 9216
#define SB_HI 18432
#define SB_LO 36864
#define SMEM_TOT 55296

__global__ __launch_bounds__(256, 3) void k_deform_mma(float* __restrict__ out) {
    extern __shared__ char sm[];
    uint32_t sb = smem_u32(sm);
    int t    = threadIdx.x;
    int wid  = t >> 5, lane = t & 31;
    int bid  = blockIdx.x;                 // b*256 + h*2 + half
    int b    = bid >> 8;
    int rem  = bid & 255;
    int h    = rem >> 1, half = rem & 1;
    const float* xb = g_xt + ((size_t)b << 20);

    int warp_m = wid & 1;
    int warp_n = wid >> 1;
    int m0base = warp_m * 32;
    int n0base = warp_n * 32;

    float acc[2][4][4];
    #pragma unroll
    for (int i = 0; i < 2; ++i)
        #pragma unroll
        for (int j = 0; j < 4; ++j)
            #pragma unroll
            for (int q = 0; q < 4; ++q) acc[i][j][q] = 0.f;

    int lrow = (lane & 7) + ((lane >> 3) & 1) * 8;
    int lcol = (lane & 16) ? 8 : 0;

    int spx = t >> 2, sq = t & 3;          // sampling: thread -> (pixel, chunk-quad)

    for (int k = 0; k < 9; ++k) {
        __syncthreads();
        // ---- stage B tiles via cp.async (overlaps with the gather phase below) ----
        {
            const char* srcH = (const char*)(g_wbh + k*9216);
            const char* srcL = (const char*)(g_wbl + k*9216);
            #pragma unroll
            for (int j = 0; j < 4; ++j) {
                int i = t + j*256;
                cp_async16(sb + SB_HI + i*16, srcH + i*16);
            }
            #pragma unroll
            for (int j = 0; j < 4; ++j) {
                int i = t + j*256;
                cp_async16(sb + SB_LO + i*16, srcL + i*16);
            }
            if (t < 128) {
                int i = 1024 + t;
                cp_async16(sb + SB_HI + i*16, srcH + i*16);
                cp_async16(sb + SB_LO + i*16, srcL + i*16);
            }
            asm volatile("cp.async.commit_group;");
        }
        // ---- sampling: thread owns one px's params, 4 chunk-quads ----
        {
            int ppb = k*NPX + (((b << 7) + h) << 7) + half*64;
            int    pc = g_ppi[ppb + spx];
            float4 wg = g_ppw[ppb + spx];
            int y0 =  pc        & 255;
            int y1 = (pc >>  8) & 255;
            int x0 = (pc >> 16) & 255;
            int x1 = (pc >> 24) & 255;
            const float4* r00 = (const float4*)(xb + (size_t)(((y0<<7)+x0)<<6)) + sq;
            const float4* r01 = (const float4*)(xb + (size_t)(((y0<<7)+x1)<<6)) + sq;
            const float4* r10 = (const float4*)(xb + (size_t)(((y1<<7)+x0)<<6)) + sq;
            const float4* r11 = (const float4*)(xb + (size_t)(((y1<<7)+x1)<<6)) + sq;
            #pragma unroll
            for (int j = 0; j < 4; ++j) {
                float4 a = r00[4*j], bb = r01[4*j], cc = r10[4*j], dd = r11[4*j];
                float4 v;
                v.x = wg.x*a.x + wg.y*bb.x + wg.z*cc.x + wg.w*dd.x;
                v.y = wg.x*a.y + wg.y*bb.y + wg.z*cc.y + wg.w*dd.y;
                v.z = wg.x*a.z + wg.y*bb.z + wg.z*cc.z + wg.w*dd.z;
                v.w = wg.x*a.w + wg.y*bb.w + wg.z*cc.w + wg.w*dd.w;
                __nv_bfloat16 hx = __float2bfloat16_rn(v.x), hy = __float2bfloat16_rn(v.y);
                __nv_bfloat16 hz = __float2bfloat16_rn(v.z), hw = __float2bfloat16_rn(v.w);
                __nv_bfloat16 lx2 = __float2bfloat16_rn(v.x - __bfloat162float(hx));
                __nv_bfloat16 ly2 = __float2bfloat16_rn(v.y - __bfloat162float(hy));
                __nv_bfloat16 lz2 = __float2bfloat16_rn(v.z - __bfloat162float(hz));
                __nv_bfloat16 lw2 = __float2bfloat16_rn(v.w - __bfloat162float(hw));
                uint32_t h01 = ((uint32_t)__bfloat16_as_ushort(hy) << 16) | __bfloat16_as_ushort(hx);
                uint32_t h23 = ((uint32_t)__bfloat16_as_ushort(hw) << 16) | __bfloat16_as_ushort(hz);
                uint32_t l01 = ((uint32_t)__bfloat16_as_ushort(ly2) << 16) | __bfloat16_as_ushort(lx2);
                uint32_t l23 = ((uint32_t)__bfloat16_as_ushort(lw2) << 16) | __bfloat16_as_ushort(lz2);
                int off = spx*144 + (sq + 4*j)*8;
                *(uint2*)(sm + SA_HI + off) = make_uint2(h01, h23);
                *(uint2*)(sm + SA_LO + off) = make_uint2(l01, l23);
            }
        }
        asm volatile("cp.async.wait_group 0;" ::: "memory");
        __syncthreads();

        // ---- MMA: 4 ksteps of 16, split passes ----
        #pragma unroll
        for (int ks = 0; ks < 4; ++ks) {
            int kc = ks*16 + lcol;
            uint32_t ah[2][4], al[2][4];
            #pragma unroll
            for (int mt = 0; mt < 2; ++mt) {
                uint32_t aoff = (uint32_t)((m0base + mt*16 + lrow)*144 + kc*2);
                ldsm_x4(ah[mt], sb + SA_HI + aoff);
                ldsm_x4(al[mt], sb + SA_LO + aoff);
            }
            #pragma unroll
            for (int ng = 0; ng < 2; ++ng) {
                uint32_t bh[4], bl[4];
                uint32_t boff = (uint32_t)((n0base + ng*16 + lrow)*144 + kc*2);
                ldsm_x4(bh, sb + SB_HI + boff);
                ldsm_x4(bl, sb + SB_LO + boff);
                #pragma unroll
                for (int mt = 0; mt < 2; ++mt) {
                    mma16816(acc[mt][2*ng],   ah[mt], bh[0], bh[2]);
                    mma16816(acc[mt][2*ng+1], ah[mt], bh[1], bh[3]);
                    mma16816(acc[mt][2*ng],   al[mt], bh[0], bh[2]);
                    mma16816(acc[mt][2*ng+1], al[mt], bh[1], bh[3]);
                    mma16816(acc[mt][2*ng],   ah[mt], bl[0], bl[2]);
                    mma16816(acc[mt][2*ng+1], ah[mt], bl[1], bl[3]);
                }
            }
        }
    }

    // ---- epilogue: frags -> smem [o][px] (pitch 68), coalesced stores ----
    __syncthreads();
    float* smo = (float*)sm;
    int qrow = lane >> 2, qcol = (lane & 3) * 2;
    #pragma unroll
    for (int mt = 0; mt < 2; ++mt) {
        #pragma unroll
        for (int nt = 0; nt < 4; ++nt) {
            int px0 = m0base + mt*16 + qrow;
            int o0  = n0base + nt*8 + qcol;
            smo[ o0     *68 + px0    ] = acc[mt][nt][0];
            smo[(o0 + 1)*68 + px0    ] = acc[mt][nt][1];
            smo[ o0     *68 + px0 + 8] = acc[mt][nt][2];
            smo[(o0 + 1)*68 + px0 + 8] = acc[mt][nt][3];
        }
    }
    __syncthreads();
    float* op = out + ((size_t)b*128)*16384 + (size_t)h*128 + half*64;
    #pragma unroll
    for (int j = 0; j < 8; ++j) {
        int idx = t + j*256;
        int o = idx >> 4, pq = idx & 15;
        float4 v = *(const float4*)(smo + o*68 + pq*4);
        *(float4*)(op + (size_t)o*16384 + pq*4) = v;
    }
}

// ---------------- launch ----------------
extern "C" void kernel_launch(void* const* d_in, const int* in_sizes, int n_in,
                              void* d_out, int out_size) {
    const float* x      = (const float*)d_in[0];
    const float* w_off  = (const float*)d_in[1];
    const float* b_off  = (const float*)d_in[2];
    const float* w_mask = (const float*)d_in[3];
    const float* b_mask = (const float*)d_in[4];
    const float* weight = (const float*)d_in[5];
    float* out = (float*)d_out;

    (void)cudaFuncSetAttribute(k_deform_mma, cudaFuncAttributeMaxDynamicSharedMemorySize, SMEM_TOT);
    (void)cudaFuncSetAttribute(k_offset_mma, cudaFuncAttributeMaxDynamicSharedMemorySize, OSMEM_TOT);

    k_transpose_x<<<512, 256>>>(x);
    k_wsplit<<<(9*128*72 + 9*32*72 + 255)/256, 256>>>(weight, w_off, w_mask);
    k_offset_mma<<<512, 256, OSMEM_TOT>>>(b_off, b_mask);
    k_deform_mma<<<1024, 256, SMEM_TOT>>>(out);
}